// round 1
// baseline (speedup 1.0000x reference)
#include <cuda_runtime.h>
#include <math.h>

#define NN     50000
#define EE     800000
#define FIN    128
#define HID    32
#define HEADS  4
#define C1     128      // HEADS*HID
#define NCLS   16
#define NEG    0.2f

// ---------------- scratch (device globals; no allocation allowed) -----------
__device__ __align__(16) float    g_h1  [NN * C1];
__device__ __align__(16) float    g_als1[NN * HEADS];
__device__ __align__(16) float    g_ald1[NN * HEADS];
__device__ __align__(16) unsigned g_m1  [NN * HEADS];
__device__ __align__(16) float    g_den1[NN * HEADS];
__device__ __align__(16) float    g_agg1[NN * C1];
__device__ __align__(16) float    g_act [NN * C1];
__device__ __align__(16) float    g_h2  [NN * NCLS];
__device__ __align__(16) float    g_als2[NN];
__device__ __align__(16) float    g_ald2[NN];
__device__ __align__(16) unsigned g_m2  [NN];
__device__ __align__(16) float    g_den2[NN];
__device__ __align__(16) float    g_agg2[NN * NCLS];

// ---------------- helpers ----------------------------------------------------
__device__ __forceinline__ float lrelu(float v) { return v > 0.f ? v : NEG * v; }

// order-preserving float<->uint for atomicMax
__device__ __forceinline__ unsigned f2o(float f) {
    unsigned u = __float_as_uint(f);
    return (u & 0x80000000u) ? ~u : (u | 0x80000000u);
}
__device__ __forceinline__ float o2f(unsigned u) {
    return (u & 0x80000000u) ? __uint_as_float(u & 0x7fffffffu)
                             : __uint_as_float(~u);
}

__device__ __forceinline__ void red_add_v4(float* addr, float a, float b, float c, float d) {
    asm volatile("red.global.add.v4.f32 [%0], {%1,%2,%3,%4};"
                 :: "l"(addr), "f"(a), "f"(b), "f"(c), "f"(d) : "memory");
}
__device__ __forceinline__ void red_add_f(float* addr, float v) {
    asm volatile("red.global.add.f32 [%0], %1;" :: "l"(addr), "f"(v) : "memory");
}

// ---------------- GEMM1: h1 = x @ W1 ; als1/ald1 epilogue --------------------
// block = 128 threads; 16 nodes per block (50000 = 3125*16 exactly).
// thread layout: cg = tid&31 (4 output cols: 4*cg..4*cg+3), ng = tid>>5 (4 nodes)
__global__ void k_gemm1(const float* __restrict__ x, const float* __restrict__ W1,
                        const float* __restrict__ a_src, const float* __restrict__ a_dst) {
    __shared__ float4 w1s[64 * 32];        // 64 k-rows x 128 cols (as float4)  32KB
    __shared__ float  xs[16][128];         // 8KB
    const int tid = threadIdx.x;
    const int cg  = tid & 31;
    const int ng  = tid >> 5;
    const int nb  = blockIdx.x * 16;

    for (int i = tid; i < 16 * 128; i += 128) {
        int n = i >> 7, k = i & 127;
        xs[n][k] = x[(nb + n) * 128 + k];
    }

    float acc[4][4];
#pragma unroll
    for (int i = 0; i < 4; i++)
#pragma unroll
        for (int j = 0; j < 4; j++) acc[i][j] = 0.f;

    for (int kb = 0; kb < 2; kb++) {
        __syncthreads();
        const float4* W4 = (const float4*)(W1 + kb * 64 * 128);
        for (int i = tid; i < 2048; i += 128) w1s[i] = W4[i];
        __syncthreads();
#pragma unroll 4
        for (int k = 0; k < 64; k++) {
            float4 w = w1s[k * 32 + cg];
#pragma unroll
            for (int i = 0; i < 4; i++) {
                float xv = xs[ng * 4 + i][kb * 64 + k];
                acc[i][0] = fmaf(xv, w.x, acc[i][0]);
                acc[i][1] = fmaf(xv, w.y, acc[i][1]);
                acc[i][2] = fmaf(xv, w.z, acc[i][2]);
                acc[i][3] = fmaf(xv, w.w, acc[i][3]);
            }
        }
    }

    // a_src1/a_dst1 are [HEADS][HID] contiguous = 128 floats, index == column c
    float as0 = a_src[cg * 4 + 0], as1 = a_src[cg * 4 + 1],
          as2 = a_src[cg * 4 + 2], as3 = a_src[cg * 4 + 3];
    float ad0 = a_dst[cg * 4 + 0], ad1 = a_dst[cg * 4 + 1],
          ad2 = a_dst[cg * 4 + 2], ad3 = a_dst[cg * 4 + 3];

#pragma unroll
    for (int i = 0; i < 4; i++) {
        int n = nb + ng * 4 + i;
        float4 hv = make_float4(acc[i][0], acc[i][1], acc[i][2], acc[i][3]);
        *(float4*)(g_h1 + n * 128 + cg * 4) = hv;
        float ps = acc[i][0] * as0 + acc[i][1] * as1 + acc[i][2] * as2 + acc[i][3] * as3;
        float pd = acc[i][0] * ad0 + acc[i][1] * ad1 + acc[i][2] * ad2 + acc[i][3] * ad3;
#pragma unroll
        for (int m = 4; m >= 1; m >>= 1) {
            ps += __shfl_xor_sync(0xffffffffu, ps, m, 8);
            pd += __shfl_xor_sync(0xffffffffu, pd, m, 8);
        }
        if ((cg & 7) == 0) {
            int h = cg >> 3;
            g_als1[n * 4 + h] = ps;
            g_ald1[n * 4 + h] = pd;
        }
    }
}

// ---------------- layer-1 softmax/aggregation kernels ------------------------
__global__ void k_initm1() {
    int i = blockIdx.x * blockDim.x + threadIdx.x;
    if (i < NN * HEADS) g_m1[i] = f2o(lrelu(g_als1[i] + g_ald1[i]));
}

__global__ void k_emax1(const int* __restrict__ ei) {
    int e = blockIdx.x * blockDim.x + threadIdx.x;
    if (e >= EE) return;
    int s = __ldg(ei + e), d = __ldg(ei + EE + e);
    float4 as = *(const float4*)(g_als1 + s * 4);
    float4 ad = *(const float4*)(g_ald1 + d * 4);
    atomicMax(g_m1 + d * 4 + 0, f2o(lrelu(as.x + ad.x)));
    atomicMax(g_m1 + d * 4 + 1, f2o(lrelu(as.y + ad.y)));
    atomicMax(g_m1 + d * 4 + 2, f2o(lrelu(as.z + ad.z)));
    atomicMax(g_m1 + d * 4 + 3, f2o(lrelu(as.w + ad.w)));
}

__global__ void k_initacc1() {
    int i = blockIdx.x * blockDim.x + threadIdx.x;
    if (i >= NN * C1) return;
    int n = i >> 7, c = i & 127, h = c >> 5;
    float self = lrelu(g_als1[n * 4 + h] + g_ald1[n * 4 + h]);
    float es = __expf(self - o2f(g_m1[n * 4 + h]));
    g_agg1[i] = es * g_h1[i];
    if ((c & 31) == 0) g_den1[n * 4 + h] = es;
}

// one warp per edge: 32 lanes x float4 = 128 channels
__global__ void k_eagg1(const int* __restrict__ ei) {
    int w = (blockIdx.x * blockDim.x + threadIdx.x) >> 5;
    int lane = threadIdx.x & 31;
    if (w >= EE) return;
    int s = __ldg(ei + w), d = __ldg(ei + EE + w);
    float4 as = *(const float4*)(g_als1 + s * 4);
    float4 ad = *(const float4*)(g_ald1 + d * 4);
    uint4  mu = *(const uint4*)(g_m1 + d * 4);
    float ex0 = __expf(lrelu(as.x + ad.x) - o2f(mu.x));
    float ex1 = __expf(lrelu(as.y + ad.y) - o2f(mu.y));
    float ex2 = __expf(lrelu(as.z + ad.z) - o2f(mu.z));
    float ex3 = __expf(lrelu(as.w + ad.w) - o2f(mu.w));
    float exl = (lane < 8) ? ex0 : (lane < 16) ? ex1 : (lane < 24) ? ex2 : ex3;
    float4 hv = *(const float4*)(g_h1 + s * 128 + lane * 4);
    red_add_v4(g_agg1 + d * 128 + lane * 4,
               hv.x * exl, hv.y * exl, hv.z * exl, hv.w * exl);
    if (lane == 0) red_add_v4(g_den1 + d * 4, ex0, ex1, ex2, ex3);
}

__global__ void k_post1(const float* __restrict__ b1) {
    int i = blockIdx.x * blockDim.x + threadIdx.x;
    if (i >= NN * C1) return;
    int n = i >> 7, c = i & 127, h = c >> 5;
    float v = g_agg1[i] / g_den1[n * 4 + h] + b1[c];
    g_act[i] = v > 0.f ? v : expm1f(v);   // ELU(alpha=1)
}

// ---------------- GEMM2: h2 = act @ W2 ; als2/ald2 epilogue ------------------
// block = 256 threads = 16 nodes x 16 classes
__global__ void k_gemm2(const float* __restrict__ W2, const float* __restrict__ a_src2,
                        const float* __restrict__ a_dst2) {
    __shared__ float w2s[128 * 16];
    __shared__ float xs[16][129];
    const int tid = threadIdx.x;
    const int nb  = blockIdx.x * 16;
    for (int i = tid; i < 2048; i += 256) w2s[i] = W2[i];
    for (int i = tid; i < 2048; i += 256) {
        int n = i >> 7, k = i & 127;
        xs[n][k] = g_act[(nb + n) * 128 + k];
    }
    __syncthreads();
    int nl = tid >> 4, c = tid & 15;
    float acc = 0.f;
#pragma unroll 8
    for (int k = 0; k < 128; k++) acc = fmaf(xs[nl][k], w2s[k * 16 + c], acc);
    int n = nb + nl;
    g_h2[n * 16 + c] = acc;
    float ps = acc * a_src2[c], pd = acc * a_dst2[c];
#pragma unroll
    for (int m = 8; m >= 1; m >>= 1) {
        ps += __shfl_xor_sync(0xffffffffu, ps, m, 16);
        pd += __shfl_xor_sync(0xffffffffu, pd, m, 16);
    }
    if (c == 0) { g_als2[n] = ps; g_ald2[n] = pd; }
}

// ---------------- layer-2 softmax/aggregation kernels ------------------------
__global__ void k_initm2() {
    int i = blockIdx.x * blockDim.x + threadIdx.x;
    if (i < NN) g_m2[i] = f2o(lrelu(g_als2[i] + g_ald2[i]));
}

__global__ void k_emax2(const int* __restrict__ ei) {
    int e = blockIdx.x * blockDim.x + threadIdx.x;
    if (e >= EE) return;
    int s = __ldg(ei + e), d = __ldg(ei + EE + e);
    atomicMax(g_m2 + d, f2o(lrelu(g_als2[s] + g_ald2[d])));
}

__global__ void k_initacc2() {
    int i = blockIdx.x * blockDim.x + threadIdx.x;
    if (i >= NN * NCLS) return;
    int n = i >> 4, c = i & 15;
    float self = lrelu(g_als2[n] + g_ald2[n]);
    float es = __expf(self - o2f(g_m2[n]));
    g_agg2[i] = es * g_h2[i];
    if (c == 0) g_den2[n] = es;
}

__global__ void k_eagg2(const int* __restrict__ ei) {
    int e = blockIdx.x * blockDim.x + threadIdx.x;
    if (e >= EE) return;
    int s = __ldg(ei + e), d = __ldg(ei + EE + e);
    float ex = __expf(lrelu(g_als2[s] + g_ald2[d]) - o2f(g_m2[d]));
#pragma unroll
    for (int j = 0; j < 4; j++) {
        float4 hv = *(const float4*)(g_h2 + s * 16 + j * 4);
        red_add_v4(g_agg2 + d * 16 + j * 4,
                   hv.x * ex, hv.y * ex, hv.z * ex, hv.w * ex);
    }
    red_add_f(g_den2 + d, ex);
}

// ---------------- final: bias + log_softmax ----------------------------------
// block 256 = 16 nodes x 16 classes
__global__ void k_final(const float* __restrict__ b2, float* __restrict__ out) {
    int tid = threadIdx.x;
    int nl = tid >> 4, c = tid & 15;
    int n = blockIdx.x * 16 + nl;
    float v = g_agg2[n * 16 + c] / g_den2[n] + b2[c];
    float mx = v;
#pragma unroll
    for (int m = 8; m >= 1; m >>= 1) mx = fmaxf(mx, __shfl_xor_sync(0xffffffffu, mx, m, 16));
    float s = expf(v - mx);
#pragma unroll
    for (int m = 8; m >= 1; m >>= 1) s += __shfl_xor_sync(0xffffffffu, s, m, 16);
    out[n * 16 + c] = v - mx - logf(s);
}

// ---------------- launch ------------------------------------------------------
extern "C" void kernel_launch(void* const* d_in, const int* in_sizes, int n_in,
                              void* d_out, int out_size) {
    const float* x      = (const float*)d_in[0];
    const int*   ei     = (const int*)  d_in[1];
    const float* W1     = (const float*)d_in[2];
    const float* a_src1 = (const float*)d_in[3];
    const float* a_dst1 = (const float*)d_in[4];
    const float* b1     = (const float*)d_in[5];
    const float* W2     = (const float*)d_in[6];
    const float* a_src2 = (const float*)d_in[7];
    const float* a_dst2 = (const float*)d_in[8];
    const float* b2     = (const float*)d_in[9];
    float* out = (float*)d_out;

    k_gemm1<<<3125, 128>>>(x, W1, a_src1, a_dst1);
    k_initm1<<<(NN * HEADS + 255) / 256, 256>>>();
    k_emax1<<<(EE + 255) / 256, 256>>>(ei);
    k_initacc1<<<(NN * C1 + 255) / 256, 256>>>();
    k_eagg1<<<(EE * 32 + 255) / 256, 256>>>(ei);
    k_post1<<<(NN * C1 + 255) / 256, 256>>>(b1);

    k_gemm2<<<3125, 256>>>(W2, a_src2, a_dst2);
    k_initm2<<<(NN + 255) / 256, 256>>>();
    k_emax2<<<(EE + 255) / 256, 256>>>(ei);
    k_initacc2<<<(NN * NCLS + 255) / 256, 256>>>();
    k_eagg2<<<(EE + 255) / 256, 256>>>(ei);
    k_final<<<3125, 256>>>(b2, out);
}

// round 2
// speedup vs baseline: 1.1127x; 1.1127x over previous
#include <cuda_runtime.h>
#include <math.h>

#define NN     50000
#define EE     800000
#define FIN    128
#define HID    32
#define HEADS  4
#define C1     128      // HEADS*HID
#define NCLS   16
#define NEG    0.2f
#define NEGINF_ORD 0x007FFFFFu   // f2o(-inf)

// ---------------- scratch (device globals; no allocation allowed) -----------
__device__ __align__(16) float    g_h1  [NN * C1];
__device__ __align__(16) float    g_als1[NN * HEADS];
__device__ __align__(16) float    g_ald1[NN * HEADS];
__device__ __align__(16) float    g_act [NN * C1];
__device__ __align__(16) float    g_h2  [NN * NCLS];
__device__ __align__(16) float    g_als2[NN];
__device__ __align__(16) float    g_ald2[NN];
__device__ __align__(16) unsigned g_maxu1[4];
__device__ __align__(16) unsigned g_maxu2[4];
__device__ __align__(16) int      g_deg   [NN];
__device__ __align__(16) int      g_rowptr[NN + 1];
__device__ __align__(16) int      g_cursor[NN];
__device__ __align__(16) int      g_srcl  [EE];

// ---------------- helpers ----------------------------------------------------
__device__ __forceinline__ float lrelu(float v) { return v > 0.f ? v : NEG * v; }

__device__ __forceinline__ unsigned f2o(float f) {
    unsigned u = __float_as_uint(f);
    return (u & 0x80000000u) ? ~u : (u | 0x80000000u);
}
__device__ __forceinline__ float o2f(unsigned u) {
    return (u & 0x80000000u) ? __uint_as_float(u & 0x7fffffffu)
                             : __uint_as_float(~u);
}

// ---------------- GEMM1: h1 = x @ W1 ; als1/ald1 epilogue --------------------
// block = 128 threads; 16 nodes per block (50000 = 3125*16 exactly).
__global__ void k_gemm1(const float* __restrict__ x, const float* __restrict__ W1,
                        const float* __restrict__ a_src, const float* __restrict__ a_dst) {
    // fused per-call scratch init (runs before anything that reads these)
    {
        int gt = blockIdx.x * 128 + threadIdx.x;
        if (gt < NN) g_deg[gt] = 0;
        if (gt < 4)  g_maxu1[gt] = NEGINF_ORD;
        if (gt == 4) g_maxu2[0] = NEGINF_ORD;
    }
    __shared__ float4 w1s[64 * 32];
    __shared__ float  xs[16][128];
    const int tid = threadIdx.x;
    const int cg  = tid & 31;
    const int ng  = tid >> 5;
    const int nb  = blockIdx.x * 16;

    for (int i = tid; i < 16 * 128; i += 128) {
        int n = i >> 7, k = i & 127;
        xs[n][k] = x[(nb + n) * 128 + k];
    }

    float acc[4][4];
#pragma unroll
    for (int i = 0; i < 4; i++)
#pragma unroll
        for (int j = 0; j < 4; j++) acc[i][j] = 0.f;

    for (int kb = 0; kb < 2; kb++) {
        __syncthreads();
        const float4* W4 = (const float4*)(W1 + kb * 64 * 128);
        for (int i = tid; i < 2048; i += 128) w1s[i] = W4[i];
        __syncthreads();
#pragma unroll 4
        for (int k = 0; k < 64; k++) {
            float4 w = w1s[k * 32 + cg];
#pragma unroll
            for (int i = 0; i < 4; i++) {
                float xv = xs[ng * 4 + i][kb * 64 + k];
                acc[i][0] = fmaf(xv, w.x, acc[i][0]);
                acc[i][1] = fmaf(xv, w.y, acc[i][1]);
                acc[i][2] = fmaf(xv, w.z, acc[i][2]);
                acc[i][3] = fmaf(xv, w.w, acc[i][3]);
            }
        }
    }

    float as0 = a_src[cg * 4 + 0], as1 = a_src[cg * 4 + 1],
          as2 = a_src[cg * 4 + 2], as3 = a_src[cg * 4 + 3];
    float ad0 = a_dst[cg * 4 + 0], ad1 = a_dst[cg * 4 + 1],
          ad2 = a_dst[cg * 4 + 2], ad3 = a_dst[cg * 4 + 3];

#pragma unroll
    for (int i = 0; i < 4; i++) {
        int n = nb + ng * 4 + i;
        float4 hv = make_float4(acc[i][0], acc[i][1], acc[i][2], acc[i][3]);
        *(float4*)(g_h1 + n * 128 + cg * 4) = hv;
        float ps = acc[i][0] * as0 + acc[i][1] * as1 + acc[i][2] * as2 + acc[i][3] * as3;
        float pd = acc[i][0] * ad0 + acc[i][1] * ad1 + acc[i][2] * ad2 + acc[i][3] * ad3;
#pragma unroll
        for (int m = 4; m >= 1; m >>= 1) {
            ps += __shfl_xor_sync(0xffffffffu, ps, m, 8);
            pd += __shfl_xor_sync(0xffffffffu, pd, m, 8);
        }
        if ((cg & 7) == 0) {
            int h = cg >> 3;
            g_als1[n * 4 + h] = ps;
            g_ald1[n * 4 + h] = pd;
        }
    }
}

// ---------------- count degrees + global max(als1) per head ------------------
// blocks [0,3125): degree count.  blocks [3125,3130): max-reduce als1.
__global__ void k_countmax(const int* __restrict__ ei) {
    if (blockIdx.x < 3125) {
        int e = blockIdx.x * 256 + threadIdx.x;
        int d = __ldg(ei + EE + e);
        atomicAdd(&g_deg[d], 1);
    } else {
        int t = (blockIdx.x - 3125) * 256 + threadIdx.x;   // 1280 threads
        float m0 = -1e30f, m1 = -1e30f, m2 = -1e30f, m3 = -1e30f;
        for (int n = t; n < NN; n += 1280) {
            float4 a = *(const float4*)(g_als1 + n * 4);
            m0 = fmaxf(m0, a.x); m1 = fmaxf(m1, a.y);
            m2 = fmaxf(m2, a.z); m3 = fmaxf(m3, a.w);
        }
#pragma unroll
        for (int o = 16; o >= 1; o >>= 1) {
            m0 = fmaxf(m0, __shfl_xor_sync(0xffffffffu, m0, o));
            m1 = fmaxf(m1, __shfl_xor_sync(0xffffffffu, m1, o));
            m2 = fmaxf(m2, __shfl_xor_sync(0xffffffffu, m2, o));
            m3 = fmaxf(m3, __shfl_xor_sync(0xffffffffu, m3, o));
        }
        if ((threadIdx.x & 31) == 0) {
            atomicMax(&g_maxu1[0], f2o(m0));
            atomicMax(&g_maxu1[1], f2o(m1));
            atomicMax(&g_maxu1[2], f2o(m2));
            atomicMax(&g_maxu1[3], f2o(m3));
        }
    }
}

// ---------------- single-block exclusive scan of degrees ---------------------
__global__ void k_scan() {
    __shared__ int sh[1024];
    const int CH = (NN + 1023) / 1024;   // 49
    int t = threadIdx.x;
    int base = t * CH;
    int lim = min(base + CH, NN);
    int lsum = 0;
    for (int i = base; i < lim; i++) lsum += g_deg[i];
    sh[t] = lsum; __syncthreads();
    for (int o = 1; o < 1024; o <<= 1) {
        int v = 0;
        if (t >= o) v = sh[t - o];
        __syncthreads();
        sh[t] += v;
        __syncthreads();
    }
    int run = sh[t] - lsum;   // exclusive prefix for this chunk
    for (int i = base; i < lim; i++) {
        g_rowptr[i] = run;
        g_cursor[i] = run;
        run += g_deg[i];
    }
    if (t == 0) g_rowptr[NN] = EE;
}

// ---------------- scatter src ids into CSR slots -----------------------------
__global__ void k_scatter(const int* __restrict__ ei) {
    int e = blockIdx.x * 256 + threadIdx.x;
    if (e >= EE) return;
    int s = __ldg(ei + e), d = __ldg(ei + EE + e);
    int p = atomicAdd(&g_cursor[d], 1);
    g_srcl[p] = s;
}

// ---------------- layer-1 fused aggregation: warp per dst node ---------------
// acc = sum over {self, in-edges} of exp(lrelu(als[s]+ald[d]) - m) * h1[s]
// out = ELU(acc/den + b1)
__global__ void __launch_bounds__(256) k_nodeagg1(const float* __restrict__ b1) {
    int gw = (blockIdx.x * 256 + threadIdx.x) >> 5;   // = node id, exactly NN warps
    int lane = threadIdx.x & 31;
    int head = lane >> 3;

    float ald_l = 0.f, m_l = 0.f;
    if (lane < 4) {
        ald_l = g_ald1[gw * 4 + lane];
        m_l = lrelu(o2f(g_maxu1[lane]) + ald_l);
    }
    int start = g_rowptr[gw], end = g_rowptr[gw + 1];

    float den_l = 0.f;
    float4 acc0, acc1 = make_float4(0.f, 0.f, 0.f, 0.f);

    // self loop
    {
        float v = 0.f;
        if (lane < 4) {
            v = __expf(lrelu(g_als1[gw * 4 + lane] + ald_l) - m_l);
            den_l = v;
        }
        float ex = __shfl_sync(0xffffffffu, v, head);
        float4 hv = *(const float4*)(g_h1 + gw * 128 + lane * 4);
        acc0 = make_float4(ex * hv.x, ex * hv.y, ex * hv.z, ex * hv.w);
    }

    for (int j0 = start; j0 < end; j0 += 32) {
        int idx = j0 + lane;
        int sbuf = (idx < end) ? g_srcl[idx] : 0;
        int cnt = min(32, end - j0);
        int t = 0;
        for (; t + 1 < cnt; t += 2) {
            int s0 = __shfl_sync(0xffffffffu, sbuf, t);
            int s1 = __shfl_sync(0xffffffffu, sbuf, t + 1);
            float v0 = 0.f, v1 = 0.f;
            if (lane < 4) {
                v0 = __expf(lrelu(g_als1[s0 * 4 + lane] + ald_l) - m_l);
                v1 = __expf(lrelu(g_als1[s1 * 4 + lane] + ald_l) - m_l);
                den_l += v0 + v1;
            }
            float ex0 = __shfl_sync(0xffffffffu, v0, head);
            float ex1 = __shfl_sync(0xffffffffu, v1, head);
            float4 h0 = *(const float4*)(g_h1 + s0 * 128 + lane * 4);
            float4 h1 = *(const float4*)(g_h1 + s1 * 128 + lane * 4);
            acc0.x = fmaf(ex0, h0.x, acc0.x); acc0.y = fmaf(ex0, h0.y, acc0.y);
            acc0.z = fmaf(ex0, h0.z, acc0.z); acc0.w = fmaf(ex0, h0.w, acc0.w);
            acc1.x = fmaf(ex1, h1.x, acc1.x); acc1.y = fmaf(ex1, h1.y, acc1.y);
            acc1.z = fmaf(ex1, h1.z, acc1.z); acc1.w = fmaf(ex1, h1.w, acc1.w);
        }
        if (t < cnt) {
            int s0 = __shfl_sync(0xffffffffu, sbuf, t);
            float v0 = 0.f;
            if (lane < 4) {
                v0 = __expf(lrelu(g_als1[s0 * 4 + lane] + ald_l) - m_l);
                den_l += v0;
            }
            float ex0 = __shfl_sync(0xffffffffu, v0, head);
            float4 h0 = *(const float4*)(g_h1 + s0 * 128 + lane * 4);
            acc0.x = fmaf(ex0, h0.x, acc0.x); acc0.y = fmaf(ex0, h0.y, acc0.y);
            acc0.z = fmaf(ex0, h0.z, acc0.z); acc0.w = fmaf(ex0, h0.w, acc0.w);
        }
    }
    acc0.x += acc1.x; acc0.y += acc1.y; acc0.z += acc1.z; acc0.w += acc1.w;

    float den = __shfl_sync(0xffffffffu, den_l, head);
    float4 bb = *(const float4*)(b1 + lane * 4);
    float4 r;
    r.x = acc0.x / den + bb.x;  r.x = r.x > 0.f ? r.x : expm1f(r.x);
    r.y = acc0.y / den + bb.y;  r.y = r.y > 0.f ? r.y : expm1f(r.y);
    r.z = acc0.z / den + bb.z;  r.z = r.z > 0.f ? r.z : expm1f(r.z);
    r.w = acc0.w / den + bb.w;  r.w = r.w > 0.f ? r.w : expm1f(r.w);
    *(float4*)(g_act + gw * 128 + lane * 4) = r;
}

// ---------------- GEMM2: h2 = act @ W2 ; als2/ald2 + global max --------------
__global__ void k_gemm2(const float* __restrict__ W2, const float* __restrict__ a_src2,
                        const float* __restrict__ a_dst2) {
    __shared__ float w2s[128 * 16];
    __shared__ float xs[16][129];
    __shared__ float s_ps[16];
    const int tid = threadIdx.x;
    const int nb  = blockIdx.x * 16;
    for (int i = tid; i < 2048; i += 256) w2s[i] = W2[i];
    for (int i = tid; i < 2048; i += 256) {
        int n = i >> 7, k = i & 127;
        xs[n][k] = g_act[(nb + n) * 128 + k];
    }
    __syncthreads();
    int nl = tid >> 4, c = tid & 15;
    float acc = 0.f;
#pragma unroll 8
    for (int k = 0; k < 128; k++) acc = fmaf(xs[nl][k], w2s[k * 16 + c], acc);
    int n = nb + nl;
    g_h2[n * 16 + c] = acc;
    float ps = acc * a_src2[c], pd = acc * a_dst2[c];
#pragma unroll
    for (int m = 8; m >= 1; m >>= 1) {
        ps += __shfl_xor_sync(0xffffffffu, ps, m, 16);
        pd += __shfl_xor_sync(0xffffffffu, pd, m, 16);
    }
    if (c == 0) {
        g_als2[n] = ps; g_ald2[n] = pd;
        s_ps[nl] = ps;
    }
    __syncthreads();
    if (tid == 0) {
        float m = s_ps[0];
#pragma unroll
        for (int i = 1; i < 16; i++) m = fmaxf(m, s_ps[i]);
        atomicMax(&g_maxu2[0], f2o(m));
    }
}

// ---------------- layer-2 fused aggregation + log_softmax --------------------
// warp per node; lanes split into 2 halves processing 2 edges in parallel,
// lane handles class (lane&15).
__global__ void __launch_bounds__(256) k_nodeagg2(const float* __restrict__ b2,
                                                  float* __restrict__ out) {
    int gw = (blockIdx.x * 256 + threadIdx.x) >> 5;
    int lane = threadIdx.x & 31;
    int sub = lane >> 4, c = lane & 15;

    float ald = g_ald2[gw];
    float m = lrelu(o2f(g_maxu2[0]) + ald);
    int start = g_rowptr[gw], end = g_rowptr[gw + 1];

    float acc = 0.f, den_l = 0.f;

    // self loop (half 0 only)
    {
        float v = 0.f;
        if (lane == 0) { v = __expf(lrelu(g_als2[gw] + ald) - m); den_l = v; }
        float ex = __shfl_sync(0xffffffffu, v, 0);
        float hv = (sub == 0) ? g_h2[gw * 16 + c] : 0.f;
        acc = ex * hv;
    }

    for (int j0 = start; j0 < end; j0 += 32) {
        int idx = j0 + lane;
        int sbuf = (idx < end) ? g_srcl[idx] : 0;
        int cnt = min(32, end - j0);
        for (int t = 0; t < cnt; t += 2) {
            int s0 = __shfl_sync(0xffffffffu, sbuf, t);
            int s1 = (t + 1 < cnt) ? __shfl_sync(0xffffffffu, sbuf, t + 1) : -1;
            int s = sub ? s1 : s0;
            float v = 0.f;
            if ((lane == 0 || lane == 16) && s >= 0) {
                v = __expf(lrelu(g_als2[s] + ald) - m);
                den_l += v;
            }
            float ex = __shfl_sync(0xffffffffu, v, sub << 4);
            float hv = (s >= 0) ? g_h2[s * 16 + c] : 0.f;
            acc = fmaf(ex, hv, acc);
        }
    }
    acc += __shfl_xor_sync(0xffffffffu, acc, 16);
    float den = __shfl_sync(0xffffffffu, den_l, 0) + __shfl_sync(0xffffffffu, den_l, 16);

    float v = acc / den + b2[c];
    float mx = v;
#pragma unroll
    for (int o = 8; o >= 1; o >>= 1) mx = fmaxf(mx, __shfl_xor_sync(0xffffffffu, mx, o, 16));
    float s = __expf(v - mx);
#pragma unroll
    for (int o = 8; o >= 1; o >>= 1) s += __shfl_xor_sync(0xffffffffu, s, o, 16);
    if (lane < 16) out[gw * 16 + c] = v - mx - logf(s);
}

// ---------------- launch ------------------------------------------------------
extern "C" void kernel_launch(void* const* d_in, const int* in_sizes, int n_in,
                              void* d_out, int out_size) {
    const float* x      = (const float*)d_in[0];
    const int*   ei     = (const int*)  d_in[1];
    const float* W1     = (const float*)d_in[2];
    const float* a_src1 = (const float*)d_in[3];
    const float* a_dst1 = (const float*)d_in[4];
    const float* b1     = (const float*)d_in[5];
    const float* W2     = (const float*)d_in[6];
    const float* a_src2 = (const float*)d_in[7];
    const float* a_dst2 = (const float*)d_in[8];
    const float* b2     = (const float*)d_in[9];
    float* out = (float*)d_out;

    k_gemm1  <<<3125, 128>>>(x, W1, a_src1, a_dst1);
    k_countmax<<<3130, 256>>>(ei);
    k_scan   <<<1, 1024>>>();
    k_scatter<<<3125, 256>>>(ei);
    k_nodeagg1<<<6250, 256>>>(b1);
    k_gemm2  <<<3125, 256>>>(W2, a_src2, a_dst2);
    k_nodeagg2<<<6250, 256>>>(b2, out);
}

// round 3
// speedup vs baseline: 1.8395x; 1.6533x over previous
#include <cuda_runtime.h>
#include <math.h>

#define NN     50000
#define EE     800000
#define FIN    128
#define HID    32
#define HEADS  4
#define C1     128      // HEADS*HID
#define NCLS   16
#define NEG    0.2f
#define NEGINF_ORD 0x007FFFFFu   // f2o(-inf)

// ---------------- scratch (device globals; no allocation allowed) -----------
__device__ __align__(16) float    g_h1  [NN * C1];
__device__ __align__(16) float    g_als1[NN * HEADS];
__device__ __align__(16) float    g_ald1[NN * HEADS];
__device__ __align__(16) float    g_act [NN * C1];
__device__ __align__(16) float    g_h2  [NN * NCLS];
__device__ __align__(16) float    g_als2[NN];
__device__ __align__(16) float    g_ald2[NN];
__device__ __align__(16) unsigned g_maxu1[4];
__device__ __align__(16) unsigned g_maxu2[4];
__device__ __align__(16) int      g_deg   [NN];
__device__ __align__(16) int      g_rowptr[NN + 1];
__device__ __align__(16) int      g_cursor[NN];
__device__ __align__(16) int      g_srcl  [EE];
__device__ __align__(16) int      g_btot  [64];
__device__ __align__(16) int      g_boff  [64];

// ---------------- helpers ----------------------------------------------------
__device__ __forceinline__ float lrelu(float v) { return v > 0.f ? v : NEG * v; }

__device__ __forceinline__ unsigned f2o(float f) {
    unsigned u = __float_as_uint(f);
    return (u & 0x80000000u) ? ~u : (u | 0x80000000u);
}
__device__ __forceinline__ float o2f(unsigned u) {
    return (u & 0x80000000u) ? __uint_as_float(u & 0x7fffffffu)
                             : __uint_as_float(~u);
}

// ---------------- GEMM1: h1 = x @ W1 ; als1/ald1 epilogue --------------------
// block = 256 threads; 32 nodes per block; grid 1563 (tail block: 16 nodes).
__global__ void __launch_bounds__(256) k_gemm1(const float* __restrict__ x,
                        const float* __restrict__ W1,
                        const float* __restrict__ a_src, const float* __restrict__ a_dst) {
    // fused per-call scratch init
    {
        int gt = blockIdx.x * 256 + threadIdx.x;
        if (gt < NN) g_deg[gt] = 0;
        if (gt < 4)  g_maxu1[gt] = NEGINF_ORD;
        if (gt == 4) g_maxu2[0] = NEGINF_ORD;
    }
    __shared__ float4 w1s[2048];      // 64 k-rows x 128 cols (float4)  32KB
    __shared__ float  xs[32][128];    // 16KB
    const int tid = threadIdx.x;
    const int cg  = tid & 31;
    const int ng  = tid >> 5;
    const int nb  = blockIdx.x * 32;

    for (int i = tid; i < 1024; i += 256) {
        int n = i >> 5, q = i & 31;
        float4 v = (nb + n < NN) ? *(const float4*)(x + (nb + n) * 128 + q * 4)
                                 : make_float4(0.f, 0.f, 0.f, 0.f);
        *(float4*)&xs[n][q * 4] = v;
    }

    float acc[4][4];
#pragma unroll
    for (int i = 0; i < 4; i++)
#pragma unroll
        for (int j = 0; j < 4; j++) acc[i][j] = 0.f;

    for (int kb = 0; kb < 2; kb++) {
        __syncthreads();
        const float4* W4 = (const float4*)(W1 + kb * 64 * 128);
        for (int i = tid; i < 2048; i += 256) w1s[i] = W4[i];
        __syncthreads();
#pragma unroll 4
        for (int k = 0; k < 64; k++) {
            float4 w = w1s[k * 32 + cg];
#pragma unroll
            for (int i = 0; i < 4; i++) {
                float xv = xs[ng * 4 + i][kb * 64 + k];
                acc[i][0] = fmaf(xv, w.x, acc[i][0]);
                acc[i][1] = fmaf(xv, w.y, acc[i][1]);
                acc[i][2] = fmaf(xv, w.z, acc[i][2]);
                acc[i][3] = fmaf(xv, w.w, acc[i][3]);
            }
        }
    }

    float as0 = a_src[cg * 4 + 0], as1 = a_src[cg * 4 + 1],
          as2 = a_src[cg * 4 + 2], as3 = a_src[cg * 4 + 3];
    float ad0 = a_dst[cg * 4 + 0], ad1 = a_dst[cg * 4 + 1],
          ad2 = a_dst[cg * 4 + 2], ad3 = a_dst[cg * 4 + 3];

#pragma unroll
    for (int i = 0; i < 4; i++) {
        int n = nb + ng * 4 + i;
        if (n >= NN) continue;
        float4 hv = make_float4(acc[i][0], acc[i][1], acc[i][2], acc[i][3]);
        *(float4*)(g_h1 + n * 128 + cg * 4) = hv;
        float ps = acc[i][0] * as0 + acc[i][1] * as1 + acc[i][2] * as2 + acc[i][3] * as3;
        float pd = acc[i][0] * ad0 + acc[i][1] * ad1 + acc[i][2] * ad2 + acc[i][3] * ad3;
#pragma unroll
        for (int m = 4; m >= 1; m >>= 1) {
            ps += __shfl_xor_sync(0xffffffffu, ps, m, 8);
            pd += __shfl_xor_sync(0xffffffffu, pd, m, 8);
        }
        if ((cg & 7) == 0) {
            int h = cg >> 3;
            g_als1[n * 4 + h] = ps;
            g_ald1[n * 4 + h] = pd;
        }
    }
}

// ---------------- count degrees (x4 ILP) + global max(als1) per head ---------
// blocks [0,782): degree count (4 edges/thread).  blocks [782,787): max-reduce.
__global__ void k_countmax(const int* __restrict__ ei) {
    if (blockIdx.x < 782) {
        int e0 = (blockIdx.x * 256 + threadIdx.x) * 4;
        if (e0 < EE) {
            int4 d4 = *(const int4*)(ei + EE + e0);
            atomicAdd(&g_deg[d4.x], 1);
            atomicAdd(&g_deg[d4.y], 1);
            atomicAdd(&g_deg[d4.z], 1);
            atomicAdd(&g_deg[d4.w], 1);
        }
    } else {
        int t = (blockIdx.x - 782) * 256 + threadIdx.x;   // 1280 threads
        float m0 = -1e30f, m1 = -1e30f, m2 = -1e30f, m3 = -1e30f;
        for (int n = t; n < NN; n += 1280) {
            float4 a = *(const float4*)(g_als1 + n * 4);
            m0 = fmaxf(m0, a.x); m1 = fmaxf(m1, a.y);
            m2 = fmaxf(m2, a.z); m3 = fmaxf(m3, a.w);
        }
#pragma unroll
        for (int o = 16; o >= 1; o >>= 1) {
            m0 = fmaxf(m0, __shfl_xor_sync(0xffffffffu, m0, o));
            m1 = fmaxf(m1, __shfl_xor_sync(0xffffffffu, m1, o));
            m2 = fmaxf(m2, __shfl_xor_sync(0xffffffffu, m2, o));
            m3 = fmaxf(m3, __shfl_xor_sync(0xffffffffu, m3, o));
        }
        if ((threadIdx.x & 31) == 0) {
            atomicMax(&g_maxu1[0], f2o(m0));
            atomicMax(&g_maxu1[1], f2o(m1));
            atomicMax(&g_maxu1[2], f2o(m2));
            atomicMax(&g_maxu1[3], f2o(m3));
        }
    }
}

// ---------------- 3-phase parallel scan of degrees ---------------------------
__global__ void k_scanA() {
    __shared__ int sw[32];
    int t = threadIdx.x, b = blockIdx.x;
    int i = b * 1024 + t;
    int v = (i < NN) ? g_deg[i] : 0;
    int x = v;
#pragma unroll
    for (int o = 1; o < 32; o <<= 1) {
        int y = __shfl_up_sync(0xffffffffu, x, o);
        if ((t & 31) >= o) x += y;
    }
    if ((t & 31) == 31) sw[t >> 5] = x;
    __syncthreads();
    if (t < 32) {
        int y = sw[t];
#pragma unroll
        for (int o = 1; o < 32; o <<= 1) {
            int z = __shfl_up_sync(0xffffffffu, y, o);
            if (t >= o) y += z;
        }
        sw[t] = y;
    }
    __syncthreads();
    int off = (t >= 32) ? sw[(t >> 5) - 1] : 0;
    int incl = x + off;
    if (i < NN) g_rowptr[i] = incl - v;     // block-local exclusive
    if (t == 1023) g_btot[b] = incl;
}

__global__ void k_scanB() {    // 1 block, 64 threads, scans 49 block totals
    __shared__ int w0s;
    int t = threadIdx.x;
    int v = (t < 49) ? g_btot[t] : 0;
    int x = v;
#pragma unroll
    for (int o = 1; o < 32; o <<= 1) {
        int y = __shfl_up_sync(0xffffffffu, x, o);
        if ((t & 31) >= o) x += y;
    }
    if (t == 31) w0s = x;
    __syncthreads();
    int incl = x + ((t >= 32) ? w0s : 0);
    if (t < 49) g_boff[t] = incl - v;
}

__global__ void k_scanC() {
    int i = blockIdx.x * 256 + threadIdx.x;   // 196*256 = 50176
    if (i < NN) {
        int r = g_rowptr[i] + g_boff[i >> 10];
        g_rowptr[i] = r;
        g_cursor[i] = r;
    }
    if (i == 0) g_rowptr[NN] = EE;
}

// ---------------- scatter src ids into CSR slots (x4 ILP) --------------------
__global__ void k_scatter(const int* __restrict__ ei) {
    int e0 = (blockIdx.x * 256 + threadIdx.x) * 4;
    if (e0 >= EE) return;
    int4 s4 = *(const int4*)(ei + e0);
    int4 d4 = *(const int4*)(ei + EE + e0);
    int p0 = atomicAdd(&g_cursor[d4.x], 1);
    int p1 = atomicAdd(&g_cursor[d4.y], 1);
    int p2 = atomicAdd(&g_cursor[d4.z], 1);
    int p3 = atomicAdd(&g_cursor[d4.w], 1);
    g_srcl[p0] = s4.x;
    g_srcl[p1] = s4.y;
    g_srcl[p2] = s4.z;
    g_srcl[p3] = s4.w;
}

// ---------------- layer-1 fused aggregation: warp per dst node ---------------
__global__ void __launch_bounds__(256) k_nodeagg1(const float* __restrict__ b1) {
    __shared__ int    s_src[8][32];
    __shared__ float4 s_ex [8][32];
    int wip  = threadIdx.x >> 5;
    int gw   = (blockIdx.x * 256 + threadIdx.x) >> 5;   // node id (exactly NN warps)
    int lane = threadIdx.x & 31;
    int head = lane >> 3;

    float4 ald = *(const float4*)(g_ald1 + gw * 4);
    uint4 mu = *(const uint4*)g_maxu1;
    float4 m4;
    m4.x = lrelu(o2f(mu.x) + ald.x);
    m4.y = lrelu(o2f(mu.y) + ald.y);
    m4.z = lrelu(o2f(mu.z) + ald.z);
    m4.w = lrelu(o2f(mu.w) + ald.w);

    int start = g_rowptr[gw], end = g_rowptr[gw + 1];

    float4 den4 = make_float4(0.f, 0.f, 0.f, 0.f);
    float4 accA, accB = make_float4(0.f, 0.f, 0.f, 0.f);

    // self loop
    {
        float4 a = *(const float4*)(g_als1 + gw * 4);
        float4 e4;
        e4.x = __expf(lrelu(a.x + ald.x) - m4.x);
        e4.y = __expf(lrelu(a.y + ald.y) - m4.y);
        e4.z = __expf(lrelu(a.z + ald.z) - m4.z);
        e4.w = __expf(lrelu(a.w + ald.w) - m4.w);
        if (lane == 0) den4 = e4;
        float ex = head == 0 ? e4.x : head == 1 ? e4.y : head == 2 ? e4.z : e4.w;
        float4 hv = *(const float4*)(g_h1 + gw * 128 + lane * 4);
        accA = make_float4(ex * hv.x, ex * hv.y, ex * hv.z, ex * hv.w);
    }

    for (int j0 = start; j0 < end; j0 += 32) {
        int idx = j0 + lane;
        bool val = idx < end;
        int s = val ? g_srcl[idx] : 0;
        float4 e4 = make_float4(0.f, 0.f, 0.f, 0.f);
        if (val) {
            float4 a = *(const float4*)(g_als1 + s * 4);
            e4.x = __expf(lrelu(a.x + ald.x) - m4.x);
            e4.y = __expf(lrelu(a.y + ald.y) - m4.y);
            e4.z = __expf(lrelu(a.z + ald.z) - m4.z);
            e4.w = __expf(lrelu(a.w + ald.w) - m4.w);
            den4.x += e4.x; den4.y += e4.y; den4.z += e4.z; den4.w += e4.w;
        }
        s_src[wip][lane] = s;
        s_ex [wip][lane] = e4;
        __syncwarp();
        int cnt = min(32, end - j0);
        int t = 0;
        for (; t + 4 <= cnt; t += 4) {
            int s0 = s_src[wip][t + 0], s1 = s_src[wip][t + 1];
            int s2 = s_src[wip][t + 2], s3 = s_src[wip][t + 3];
            float e0 = ((const float*)&s_ex[wip][t + 0])[head];
            float e1 = ((const float*)&s_ex[wip][t + 1])[head];
            float e2 = ((const float*)&s_ex[wip][t + 2])[head];
            float e3 = ((const float*)&s_ex[wip][t + 3])[head];
            float4 h0 = *(const float4*)(g_h1 + s0 * 128 + lane * 4);
            float4 h1 = *(const float4*)(g_h1 + s1 * 128 + lane * 4);
            float4 h2 = *(const float4*)(g_h1 + s2 * 128 + lane * 4);
            float4 h3 = *(const float4*)(g_h1 + s3 * 128 + lane * 4);
            accA.x = fmaf(e0, h0.x, accA.x); accA.y = fmaf(e0, h0.y, accA.y);
            accA.z = fmaf(e0, h0.z, accA.z); accA.w = fmaf(e0, h0.w, accA.w);
            accB.x = fmaf(e1, h1.x, accB.x); accB.y = fmaf(e1, h1.y, accB.y);
            accB.z = fmaf(e1, h1.z, accB.z); accB.w = fmaf(e1, h1.w, accB.w);
            accA.x = fmaf(e2, h2.x, accA.x); accA.y = fmaf(e2, h2.y, accA.y);
            accA.z = fmaf(e2, h2.z, accA.z); accA.w = fmaf(e2, h2.w, accA.w);
            accB.x = fmaf(e3, h3.x, accB.x); accB.y = fmaf(e3, h3.y, accB.y);
            accB.z = fmaf(e3, h3.z, accB.z); accB.w = fmaf(e3, h3.w, accB.w);
        }
        for (; t < cnt; t++) {
            int s0 = s_src[wip][t];
            float e0 = ((const float*)&s_ex[wip][t])[head];
            float4 h0 = *(const float4*)(g_h1 + s0 * 128 + lane * 4);
            accA.x = fmaf(e0, h0.x, accA.x); accA.y = fmaf(e0, h0.y, accA.y);
            accA.z = fmaf(e0, h0.z, accA.z); accA.w = fmaf(e0, h0.w, accA.w);
        }
        __syncwarp();
    }
    accA.x += accB.x; accA.y += accB.y; accA.z += accB.z; accA.w += accB.w;

#pragma unroll
    for (int o = 16; o >= 1; o >>= 1) {
        den4.x += __shfl_xor_sync(0xffffffffu, den4.x, o);
        den4.y += __shfl_xor_sync(0xffffffffu, den4.y, o);
        den4.z += __shfl_xor_sync(0xffffffffu, den4.z, o);
        den4.w += __shfl_xor_sync(0xffffffffu, den4.w, o);
    }
    float den = head == 0 ? den4.x : head == 1 ? den4.y : head == 2 ? den4.z : den4.w;

    float4 bb = *(const float4*)(b1 + lane * 4);
    float4 r;
    r.x = accA.x / den + bb.x;  r.x = r.x > 0.f ? r.x : expm1f(r.x);
    r.y = accA.y / den + bb.y;  r.y = r.y > 0.f ? r.y : expm1f(r.y);
    r.z = accA.z / den + bb.z;  r.z = r.z > 0.f ? r.z : expm1f(r.z);
    r.w = accA.w / den + bb.w;  r.w = r.w > 0.f ? r.w : expm1f(r.w);
    *(float4*)(g_act + gw * 128 + lane * 4) = r;
}

// ---------------- GEMM2: h2 = act @ W2 ; als2/ald2 + global max --------------
__global__ void k_gemm2(const float* __restrict__ W2, const float* __restrict__ a_src2,
                        const float* __restrict__ a_dst2) {
    __shared__ float w2s[128 * 16];
    __shared__ float xs[16][129];
    __shared__ float s_ps[16];
    const int tid = threadIdx.x;
    const int nb  = blockIdx.x * 16;
    for (int i = tid; i < 2048; i += 256) w2s[i] = W2[i];
    for (int i = tid; i < 2048; i += 256) {
        int n = i >> 7, k = i & 127;
        xs[n][k] = g_act[(nb + n) * 128 + k];
    }
    __syncthreads();
    int nl = tid >> 4, c = tid & 15;
    float acc = 0.f;
#pragma unroll 8
    for (int k = 0; k < 128; k++) acc = fmaf(xs[nl][k], w2s[k * 16 + c], acc);
    int n = nb + nl;
    g_h2[n * 16 + c] = acc;
    float ps = acc * a_src2[c], pd = acc * a_dst2[c];
#pragma unroll
    for (int m = 8; m >= 1; m >>= 1) {
        ps += __shfl_xor_sync(0xffffffffu, ps, m, 16);
        pd += __shfl_xor_sync(0xffffffffu, pd, m, 16);
    }
    if (c == 0) {
        g_als2[n] = ps; g_ald2[n] = pd;
        s_ps[nl] = ps;
    }
    __syncthreads();
    if (tid == 0) {
        float m = s_ps[0];
#pragma unroll
        for (int i = 1; i < 16; i++) m = fmaxf(m, s_ps[i]);
        atomicMax(&g_maxu2[0], f2o(m));
    }
}

// ---------------- layer-2 fused aggregation + log_softmax --------------------
__global__ void __launch_bounds__(256) k_nodeagg2(const float* __restrict__ b2,
                                                  float* __restrict__ out) {
    __shared__ float s_ex2[8][32];
    __shared__ int   s_s2 [8][32];
    int wip  = threadIdx.x >> 5;
    int gw   = (blockIdx.x * 256 + threadIdx.x) >> 5;
    int lane = threadIdx.x & 31;
    int sub  = lane >> 4, c = lane & 15;

    float ald = g_ald2[gw];
    float m = lrelu(o2f(g_maxu2[0]) + ald);
    int start = g_rowptr[gw], end = g_rowptr[gw + 1];

    float acc = 0.f, den_l = 0.f;

    // self loop (count once: sub 0 accumulates, lane 0 owns den)
    {
        float exs = __expf(lrelu(g_als2[gw] + ald) - m);
        if (lane == 0) den_l = exs;
        if (sub == 0) acc = exs * g_h2[gw * 16 + c];
    }

    for (int j0 = start; j0 < end; j0 += 32) {
        int idx = j0 + lane;
        bool val = idx < end;
        int s = val ? g_srcl[idx] : 0;
        float e = 0.f;
        if (val) {
            e = __expf(lrelu(g_als2[s] + ald) - m);
            den_l += e;
        }
        s_s2 [wip][lane] = s;
        s_ex2[wip][lane] = e;
        __syncwarp();
        int cnt = min(32, end - j0);
        for (int t = 0; t < cnt; t += 4) {
            int i0 = t + sub, i1 = t + 2 + sub;
            if (i0 < cnt) {
                float e0 = s_ex2[wip][i0];
                int   s0 = s_s2 [wip][i0];
                acc = fmaf(e0, g_h2[s0 * 16 + c], acc);
            }
            if (i1 < cnt) {
                float e1 = s_ex2[wip][i1];
                int   s1 = s_s2 [wip][i1];
                acc = fmaf(e1, g_h2[s1 * 16 + c], acc);
            }
        }
        __syncwarp();
    }
    acc += __shfl_xor_sync(0xffffffffu, acc, 16);
#pragma unroll
    for (int o = 16; o >= 1; o >>= 1) den_l += __shfl_xor_sync(0xffffffffu, den_l, o);

    float v = acc / den_l + b2[c];
    float mx = v;
#pragma unroll
    for (int o = 8; o >= 1; o >>= 1) mx = fmaxf(mx, __shfl_xor_sync(0xffffffffu, mx, o, 16));
    float s = __expf(v - mx);
#pragma unroll
    for (int o = 8; o >= 1; o >>= 1) s += __shfl_xor_sync(0xffffffffu, s, o, 16);
    if (lane < 16) out[gw * 16 + c] = v - mx - logf(s);
}

// ---------------- launch ------------------------------------------------------
extern "C" void kernel_launch(void* const* d_in, const int* in_sizes, int n_in,
                              void* d_out, int out_size) {
    const float* x      = (const float*)d_in[0];
    const int*   ei     = (const int*)  d_in[1];
    const float* W1     = (const float*)d_in[2];
    const float* a_src1 = (const float*)d_in[3];
    const float* a_dst1 = (const float*)d_in[4];
    const float* b1     = (const float*)d_in[5];
    const float* W2     = (const float*)d_in[6];
    const float* a_src2 = (const float*)d_in[7];
    const float* a_dst2 = (const float*)d_in[8];
    const float* b2     = (const float*)d_in[9];
    float* out = (float*)d_out;

    k_gemm1   <<<1563, 256>>>(x, W1, a_src1, a_dst1);
    k_countmax<<<787, 256>>>(ei);
    k_scanA   <<<49, 1024>>>();
    k_scanB   <<<1, 64>>>();
    k_scanC   <<<196, 256>>>();
    k_scatter <<<782, 256>>>(ei);
    k_nodeagg1<<<6250, 256>>>(b1);
    k_gemm2   <<<3125, 256>>>(W2, a_src2, a_dst2);
    k_nodeagg2<<<6250, 256>>>(b2, out);
}

// round 4
// speedup vs baseline: 2.0429x; 1.1106x over previous
#include <cuda_runtime.h>
#include <cuda_fp16.h>
#include <math.h>

#define NN     50000
#define EE     800000
#define FIN    128
#define HID    32
#define HEADS  4
#define C1     128      // HEADS*HID
#define NCLS   16
#define NEG    0.2f
#define NEGINF_ORD 0x007FFFFFu   // f2o(-inf)

// ---------------- scratch (device globals; no allocation allowed) -----------
__device__ __align__(16) __half   g_h1h [NN * C1];
__device__ __align__(16) float    g_als1[NN * HEADS];
__device__ __align__(16) float    g_ald1[NN * HEADS];
__device__ __align__(16) float    g_act [NN * C1];
__device__ __align__(16) float    g_h2  [NN * NCLS];
__device__ __align__(16) float    g_als2[NN];
__device__ __align__(16) float    g_ald2[NN];
__device__ __align__(16) unsigned g_maxu1[4];
__device__ __align__(16) unsigned g_maxu2[4];
__device__ __align__(16) int      g_deg   [NN];
__device__ __align__(16) int      g_rowptr[NN + 1];
__device__ __align__(16) int      g_cursor[NN];
__device__ __align__(16) int      g_srcl  [EE];
__device__ __align__(16) int      g_btot  [64];
__device__ __align__(16) int      g_boff  [64];

// ---------------- helpers ----------------------------------------------------
__device__ __forceinline__ float lrelu(float v) { return v > 0.f ? v : NEG * v; }

__device__ __forceinline__ unsigned f2o(float f) {
    unsigned u = __float_as_uint(f);
    return (u & 0x80000000u) ? ~u : (u | 0x80000000u);
}
__device__ __forceinline__ float o2f(unsigned u) {
    return (u & 0x80000000u) ? __uint_as_float(u & 0x7fffffffu)
                             : __uint_as_float(~u);
}

__device__ __forceinline__ void ldm_x4(unsigned& r0, unsigned& r1, unsigned& r2, unsigned& r3,
                                       unsigned addr) {
    asm volatile("ldmatrix.sync.aligned.m8n8.x4.shared.b16 {%0,%1,%2,%3}, [%4];"
                 : "=r"(r0), "=r"(r1), "=r"(r2), "=r"(r3) : "r"(addr));
}
__device__ __forceinline__ void ldm_x4t(unsigned& r0, unsigned& r1, unsigned& r2, unsigned& r3,
                                        unsigned addr) {
    asm volatile("ldmatrix.sync.aligned.m8n8.x4.trans.shared.b16 {%0,%1,%2,%3}, [%4];"
                 : "=r"(r0), "=r"(r1), "=r"(r2), "=r"(r3) : "r"(addr));
}
__device__ __forceinline__ void mma16816(float* c, const unsigned* a, unsigned b0, unsigned b1) {
    asm volatile("mma.sync.aligned.m16n8k16.row.col.f32.f16.f16.f32 "
                 "{%0,%1,%2,%3}, {%4,%5,%6,%7}, {%8,%9}, {%0,%1,%2,%3};"
                 : "+f"(c[0]), "+f"(c[1]), "+f"(c[2]), "+f"(c[3])
                 : "r"(a[0]), "r"(a[1]), "r"(a[2]), "r"(a[3]), "r"(b0), "r"(b1));
}

// ---------------- GEMM1 via HMMA: h1h = fp16(x @ W1) ; als1/ald1 epilogue ----
// 256 threads = 8 warps; block tile M=128, N=128, K=128. Warp: 16 rows.
#define XSTR 136   // padded half stride for conflict-free ldmatrix
__global__ void __launch_bounds__(256, 2) k_gemm1h(const float* __restrict__ x,
                        const float* __restrict__ W1,
                        const float* __restrict__ a_src, const float* __restrict__ a_dst) {
    // fused per-call scratch init
    {
        int gt = blockIdx.x * 256 + threadIdx.x;
        if (gt < NN) g_deg[gt] = 0;
        if (gt < 4)  g_maxu1[gt] = NEGINF_ORD;
        if (gt == 4) g_maxu2[0] = NEGINF_ORD;
    }
    extern __shared__ __half dsm[];
    __half* xs = dsm;                 // [128][XSTR]  row m, col k
    __half* ws = dsm + 128 * XSTR;    // [128][XSTR]  row k, col n

    const int tid  = threadIdx.x;
    const int lane = tid & 31;
    const int warp = tid >> 5;
    const int nb   = blockIdx.x * 128;
    const int g    = lane >> 2;
    const int tig  = lane & 3;

    // stage + convert x (bounds: zero-fill) and W1
    for (int i = tid; i < 128 * 32; i += 256) {
        int r = i >> 5, q = i & 31;
        float4 v = (nb + r < NN) ? *(const float4*)(x + (size_t)(nb + r) * 128 + q * 4)
                                 : make_float4(0.f, 0.f, 0.f, 0.f);
        __half2* dst = (__half2*)(xs + r * XSTR + q * 4);
        dst[0] = __floats2half2_rn(v.x, v.y);
        dst[1] = __floats2half2_rn(v.z, v.w);
    }
    for (int i = tid; i < 128 * 32; i += 256) {
        int r = i >> 5, q = i & 31;
        float4 v = *(const float4*)(W1 + r * 128 + q * 4);
        __half2* dst = (__half2*)(ws + r * XSTR + q * 4);
        dst[0] = __floats2half2_rn(v.x, v.y);
        dst[1] = __floats2half2_rn(v.z, v.w);
    }
    __syncthreads();

    unsigned xs_u = (unsigned)__cvta_generic_to_shared(xs);
    unsigned ws_u = (unsigned)__cvta_generic_to_shared(ws);
    unsigned aaddr = xs_u + ((warp * 16 + (lane & 15)) * XSTR + (lane >> 4) * 8) * 2;
    unsigned baddr = ws_u + ((lane & 15) * XSTR + (lane >> 4) * 8) * 2;

    float c[16][4];
#pragma unroll
    for (int j = 0; j < 16; j++)
#pragma unroll
        for (int q = 0; q < 4; q++) c[j][q] = 0.f;

#pragma unroll
    for (int ks = 0; ks < 8; ks++) {
        unsigned a[4];
        ldm_x4(a[0], a[1], a[2], a[3], aaddr + ks * 32);
#pragma unroll
        for (int p = 0; p < 8; p++) {
            unsigned b0, b1, b2, b3;
            ldm_x4t(b0, b1, b2, b3, baddr + ks * (16 * XSTR * 2) + p * 32);
            mma16816(c[2 * p],     a, b0, b1);
            mma16816(c[2 * p + 1], a, b2, b3);
        }
    }

    // epilogue: store h1 fp16 + als/ald dot products
    int r0 = nb + warp * 16 + g;
    int r1 = r0 + 8;
    bool v0 = r0 < NN, v1 = r1 < NN;
    float ss0[4] = {0, 0, 0, 0}, sd0[4] = {0, 0, 0, 0};
    float ss1[4] = {0, 0, 0, 0}, sd1[4] = {0, 0, 0, 0};
#pragma unroll
    for (int j = 0; j < 16; j++) {
        int col = j * 8 + tig * 2;
        float a0 = a_src[col], a1 = a_src[col + 1];
        float d0 = a_dst[col], d1 = a_dst[col + 1];
        int h = j >> 2;
        ss0[h] += c[j][0] * a0 + c[j][1] * a1;
        sd0[h] += c[j][0] * d0 + c[j][1] * d1;
        ss1[h] += c[j][2] * a0 + c[j][3] * a1;
        sd1[h] += c[j][2] * d0 + c[j][3] * d1;
        if (v0) *(__half2*)(g_h1h + (size_t)r0 * 128 + col) = __floats2half2_rn(c[j][0], c[j][1]);
        if (v1) *(__half2*)(g_h1h + (size_t)r1 * 128 + col) = __floats2half2_rn(c[j][2], c[j][3]);
    }
#pragma unroll
    for (int o = 1; o <= 2; o <<= 1) {
#pragma unroll
        for (int h = 0; h < 4; h++) {
            ss0[h] += __shfl_xor_sync(0xffffffffu, ss0[h], o);
            sd0[h] += __shfl_xor_sync(0xffffffffu, sd0[h], o);
            ss1[h] += __shfl_xor_sync(0xffffffffu, ss1[h], o);
            sd1[h] += __shfl_xor_sync(0xffffffffu, sd1[h], o);
        }
    }
    if (tig == 0) {
        if (v0) {
#pragma unroll
            for (int h = 0; h < 4; h++) {
                g_als1[r0 * 4 + h] = ss0[h];
                g_ald1[r0 * 4 + h] = sd0[h];
            }
        }
        if (v1) {
#pragma unroll
            for (int h = 0; h < 4; h++) {
                g_als1[r1 * 4 + h] = ss1[h];
                g_ald1[r1 * 4 + h] = sd1[h];
            }
        }
    }
}

// ---------------- count degrees (x4 ILP) + global max(als1) per head ---------
__global__ void k_countmax(const int* __restrict__ ei) {
    if (blockIdx.x < 782) {
        int e0 = (blockIdx.x * 256 + threadIdx.x) * 4;
        if (e0 < EE) {
            int4 d4 = *(const int4*)(ei + EE + e0);
            atomicAdd(&g_deg[d4.x], 1);
            atomicAdd(&g_deg[d4.y], 1);
            atomicAdd(&g_deg[d4.z], 1);
            atomicAdd(&g_deg[d4.w], 1);
        }
    } else {
        int t = (blockIdx.x - 782) * 256 + threadIdx.x;   // 1280 threads
        float m0 = -1e30f, m1 = -1e30f, m2 = -1e30f, m3 = -1e30f;
        for (int n = t; n < NN; n += 1280) {
            float4 a = *(const float4*)(g_als1 + n * 4);
            m0 = fmaxf(m0, a.x); m1 = fmaxf(m1, a.y);
            m2 = fmaxf(m2, a.z); m3 = fmaxf(m3, a.w);
        }
#pragma unroll
        for (int o = 16; o >= 1; o >>= 1) {
            m0 = fmaxf(m0, __shfl_xor_sync(0xffffffffu, m0, o));
            m1 = fmaxf(m1, __shfl_xor_sync(0xffffffffu, m1, o));
            m2 = fmaxf(m2, __shfl_xor_sync(0xffffffffu, m2, o));
            m3 = fmaxf(m3, __shfl_xor_sync(0xffffffffu, m3, o));
        }
        if ((threadIdx.x & 31) == 0) {
            atomicMax(&g_maxu1[0], f2o(m0));
            atomicMax(&g_maxu1[1], f2o(m1));
            atomicMax(&g_maxu1[2], f2o(m2));
            atomicMax(&g_maxu1[3], f2o(m3));
        }
    }
}

// ---------------- 3-phase parallel scan of degrees ---------------------------
__global__ void k_scanA() {
    __shared__ int sw[32];
    int t = threadIdx.x, b = blockIdx.x;
    int i = b * 1024 + t;
    int v = (i < NN) ? g_deg[i] : 0;
    int x = v;
#pragma unroll
    for (int o = 1; o < 32; o <<= 1) {
        int y = __shfl_up_sync(0xffffffffu, x, o);
        if ((t & 31) >= o) x += y;
    }
    if ((t & 31) == 31) sw[t >> 5] = x;
    __syncthreads();
    if (t < 32) {
        int y = sw[t];
#pragma unroll
        for (int o = 1; o < 32; o <<= 1) {
            int z = __shfl_up_sync(0xffffffffu, y, o);
            if (t >= o) y += z;
        }
        sw[t] = y;
    }
    __syncthreads();
    int off = (t >= 32) ? sw[(t >> 5) - 1] : 0;
    int incl = x + off;
    if (i < NN) g_rowptr[i] = incl - v;     // block-local exclusive
    if (t == 1023) g_btot[b] = incl;
}

__global__ void k_scanB() {    // 1 block, 64 threads, scans 49 block totals
    __shared__ int w0s;
    int t = threadIdx.x;
    int v = (t < 49) ? g_btot[t] : 0;
    int x = v;
#pragma unroll
    for (int o = 1; o < 32; o <<= 1) {
        int y = __shfl_up_sync(0xffffffffu, x, o);
        if ((t & 31) >= o) x += y;
    }
    if (t == 31) w0s = x;
    __syncthreads();
    int incl = x + ((t >= 32) ? w0s : 0);
    if (t < 49) g_boff[t] = incl - v;
}

__global__ void k_scanC() {
    int i = blockIdx.x * 256 + threadIdx.x;   // 196*256 = 50176
    if (i < NN) {
        int r = g_rowptr[i] + g_boff[i >> 10];
        g_rowptr[i] = r;
        g_cursor[i] = r;
    }
    if (i == 0) g_rowptr[NN] = EE;
}

// ---------------- scatter src ids into CSR slots (x4 ILP) --------------------
__global__ void k_scatter(const int* __restrict__ ei) {
    int e0 = (blockIdx.x * 256 + threadIdx.x) * 4;
    if (e0 >= EE) return;
    int4 s4 = *(const int4*)(ei + e0);
    int4 d4 = *(const int4*)(ei + EE + e0);
    int p0 = atomicAdd(&g_cursor[d4.x], 1);
    int p1 = atomicAdd(&g_cursor[d4.y], 1);
    int p2 = atomicAdd(&g_cursor[d4.z], 1);
    int p3 = atomicAdd(&g_cursor[d4.w], 1);
    g_srcl[p0] = s4.x;
    g_srcl[p1] = s4.y;
    g_srcl[p2] = s4.z;
    g_srcl[p3] = s4.w;
}

// ---------------- layer-1 fused aggregation: warp per dst node ---------------
// h1 in fp16: 2 edges in flight per warp, 16 lanes x 8 channels each.
__global__ void __launch_bounds__(256) k_nodeagg1(const float* __restrict__ b1) {
    __shared__ int    s_src[8][32];
    __shared__ float4 s_ex [8][32];
    int wip  = threadIdx.x >> 5;
    int gw   = (blockIdx.x * 256 + threadIdx.x) >> 5;   // node id
    int lane = threadIdx.x & 31;
    int sub  = lane >> 4;
    int cl   = lane & 15;           // channel group: channels cl*8..cl*8+7
    int head = cl >> 2;

    float4 ald = *(const float4*)(g_ald1 + gw * 4);
    uint4 mu = *(const uint4*)g_maxu1;
    float4 m4;
    m4.x = lrelu(o2f(mu.x) + ald.x);
    m4.y = lrelu(o2f(mu.y) + ald.y);
    m4.z = lrelu(o2f(mu.z) + ald.z);
    m4.w = lrelu(o2f(mu.w) + ald.w);

    int start = g_rowptr[gw], end = g_rowptr[gw + 1];

    float4 den4 = make_float4(0.f, 0.f, 0.f, 0.f);
    float accA[8], accB[8];
#pragma unroll
    for (int j = 0; j < 8; j++) { accA[j] = 0.f; accB[j] = 0.f; }

    // self loop (sub 0 only)
    {
        float4 a = *(const float4*)(g_als1 + gw * 4);
        float4 e4;
        e4.x = __expf(lrelu(a.x + ald.x) - m4.x);
        e4.y = __expf(lrelu(a.y + ald.y) - m4.y);
        e4.z = __expf(lrelu(a.z + ald.z) - m4.z);
        e4.w = __expf(lrelu(a.w + ald.w) - m4.w);
        if (lane == 0) den4 = e4;
        if (sub == 0) {
            float ex = head == 0 ? e4.x : head == 1 ? e4.y : head == 2 ? e4.z : e4.w;
            uint4 u = *(const uint4*)(g_h1h + (size_t)gw * 128 + cl * 8);
            const __half2* hp = (const __half2*)&u;
#pragma unroll
            for (int q = 0; q < 4; q++) {
                float2 f = __half22float2(hp[q]);
                accA[q * 2]     = ex * f.x;
                accA[q * 2 + 1] = ex * f.y;
            }
        }
    }

    for (int j0 = start; j0 < end; j0 += 32) {
        int idx = j0 + lane;
        bool val = idx < end;
        int s = val ? g_srcl[idx] : 0;
        float4 e4 = make_float4(0.f, 0.f, 0.f, 0.f);
        if (val) {
            float4 a = *(const float4*)(g_als1 + s * 4);
            e4.x = __expf(lrelu(a.x + ald.x) - m4.x);
            e4.y = __expf(lrelu(a.y + ald.y) - m4.y);
            e4.z = __expf(lrelu(a.z + ald.z) - m4.z);
            e4.w = __expf(lrelu(a.w + ald.w) - m4.w);
            den4.x += e4.x; den4.y += e4.y; den4.z += e4.z; den4.w += e4.w;
        }
        s_src[wip][lane] = s;
        s_ex [wip][lane] = e4;
        __syncwarp();
        int cnt = min(32, end - j0);
        int t = 0;
        for (; t + 4 <= cnt; t += 4) {
            int iA = t + sub, iB = t + 2 + sub;
            int sA = s_src[wip][iA], sB = s_src[wip][iB];
            float eA = ((const float*)&s_ex[wip][iA])[head];
            float eB = ((const float*)&s_ex[wip][iB])[head];
            uint4 uA = *(const uint4*)(g_h1h + (size_t)sA * 128 + cl * 8);
            uint4 uB = *(const uint4*)(g_h1h + (size_t)sB * 128 + cl * 8);
            const __half2* hA = (const __half2*)&uA;
            const __half2* hB = (const __half2*)&uB;
#pragma unroll
            for (int q = 0; q < 4; q++) {
                float2 fA = __half22float2(hA[q]);
                float2 fB = __half22float2(hB[q]);
                accA[q * 2]     = fmaf(eA, fA.x, accA[q * 2]);
                accA[q * 2 + 1] = fmaf(eA, fA.y, accA[q * 2 + 1]);
                accB[q * 2]     = fmaf(eB, fB.x, accB[q * 2]);
                accB[q * 2 + 1] = fmaf(eB, fB.y, accB[q * 2 + 1]);
            }
        }
        for (; t < cnt; t += 2) {
            int i = t + sub;
            if (i < cnt) {
                int sA = s_src[wip][i];
                float eA = ((const float*)&s_ex[wip][i])[head];
                uint4 uA = *(const uint4*)(g_h1h + (size_t)sA * 128 + cl * 8);
                const __half2* hA = (const __half2*)&uA;
#pragma unroll
                for (int q = 0; q < 4; q++) {
                    float2 fA = __half22float2(hA[q]);
                    accA[q * 2]     = fmaf(eA, fA.x, accA[q * 2]);
                    accA[q * 2 + 1] = fmaf(eA, fA.y, accA[q * 2 + 1]);
                }
            }
        }
        __syncwarp();
    }

#pragma unroll
    for (int j = 0; j < 8; j++) {
        accA[j] += accB[j];
        accA[j] += __shfl_xor_sync(0xffffffffu, accA[j], 16);
    }
#pragma unroll
    for (int o = 16; o >= 1; o >>= 1) {
        den4.x += __shfl_xor_sync(0xffffffffu, den4.x, o);
        den4.y += __shfl_xor_sync(0xffffffffu, den4.y, o);
        den4.z += __shfl_xor_sync(0xffffffffu, den4.z, o);
        den4.w += __shfl_xor_sync(0xffffffffu, den4.w, o);
    }
    if (sub == 0) {
        float den = head == 0 ? den4.x : head == 1 ? den4.y : head == 2 ? den4.z : den4.w;
        float inv = 1.f / den;
        float4 ba = ((const float4*)b1)[cl * 2];
        float4 bb = ((const float4*)b1)[cl * 2 + 1];
        float4 r0, r1;
        r0.x = accA[0] * inv + ba.x;  r0.x = r0.x > 0.f ? r0.x : expm1f(r0.x);
        r0.y = accA[1] * inv + ba.y;  r0.y = r0.y > 0.f ? r0.y : expm1f(r0.y);
        r0.z = accA[2] * inv + ba.z;  r0.z = r0.z > 0.f ? r0.z : expm1f(r0.z);
        r0.w = accA[3] * inv + ba.w;  r0.w = r0.w > 0.f ? r0.w : expm1f(r0.w);
        r1.x = accA[4] * inv + bb.x;  r1.x = r1.x > 0.f ? r1.x : expm1f(r1.x);
        r1.y = accA[5] * inv + bb.y;  r1.y = r1.y > 0.f ? r1.y : expm1f(r1.y);
        r1.z = accA[6] * inv + bb.z;  r1.z = r1.z > 0.f ? r1.z : expm1f(r1.z);
        r1.w = accA[7] * inv + bb.w;  r1.w = r1.w > 0.f ? r1.w : expm1f(r1.w);
        *(float4*)(g_act + (size_t)gw * 128 + cl * 8)     = r0;
        *(float4*)(g_act + (size_t)gw * 128 + cl * 8 + 4) = r1;
    }
}

// ---------------- GEMM2: h2 = act @ W2 ; als2/ald2 + global max --------------
__global__ void k_gemm2(const float* __restrict__ W2, const float* __restrict__ a_src2,
                        const float* __restrict__ a_dst2) {
    __shared__ float w2s[128 * 16];
    __shared__ float xs[16][129];
    __shared__ float s_ps[16];
    const int tid = threadIdx.x;
    const int nb  = blockIdx.x * 16;
    for (int i = tid; i < 2048; i += 256) w2s[i] = W2[i];
    for (int i = tid; i < 2048; i += 256) {
        int n = i >> 7, k = i & 127;
        xs[n][k] = g_act[(nb + n) * 128 + k];
    }
    __syncthreads();
    int nl = tid >> 4, c = tid & 15;
    float acc = 0.f;
#pragma unroll 8
    for (int k = 0; k < 128; k++) acc = fmaf(xs[nl][k], w2s[k * 16 + c], acc);
    int n = nb + nl;
    g_h2[n * 16 + c] = acc;
    float ps = acc * a_src2[c], pd = acc * a_dst2[c];
#pragma unroll
    for (int m = 8; m >= 1; m >>= 1) {
        ps += __shfl_xor_sync(0xffffffffu, ps, m, 16);
        pd += __shfl_xor_sync(0xffffffffu, pd, m, 16);
    }
    if (c == 0) {
        g_als2[n] = ps; g_ald2[n] = pd;
        s_ps[nl] = ps;
    }
    __syncthreads();
    if (tid == 0) {
        float m = s_ps[0];
#pragma unroll
        for (int i = 1; i < 16; i++) m = fmaxf(m, s_ps[i]);
        atomicMax(&g_maxu2[0], f2o(m));
    }
}

// ---------------- layer-2 fused aggregation + log_softmax --------------------
__global__ void __launch_bounds__(256) k_nodeagg2(const float* __restrict__ b2,
                                                  float* __restrict__ out) {
    __shared__ float s_ex2[8][32];
    __shared__ int   s_s2 [8][32];
    int wip  = threadIdx.x >> 5;
    int gw   = (blockIdx.x * 256 + threadIdx.x) >> 5;
    int lane = threadIdx.x & 31;
    int sub  = lane >> 4, c = lane & 15;

    float ald = g_ald2[gw];
    float m = lrelu(o2f(g_maxu2[0]) + ald);
    int start = g_rowptr[gw], end = g_rowptr[gw + 1];

    float accA = 0.f, accB = 0.f, den_l = 0.f;

    // self loop (count once: sub 0 accumulates, lane 0 owns den)
    {
        float exs = __expf(lrelu(g_als2[gw] + ald) - m);
        if (lane == 0) den_l = exs;
        if (sub == 0) accA = exs * g_h2[gw * 16 + c];
    }

    for (int j0 = start; j0 < end; j0 += 32) {
        int idx = j0 + lane;
        bool val = idx < end;
        int s = val ? g_srcl[idx] : 0;
        float e = 0.f;
        if (val) {
            e = __expf(lrelu(g_als2[s] + ald) - m);
            den_l += e;
        }
        s_s2 [wip][lane] = s;
        s_ex2[wip][lane] = e;
        __syncwarp();
        int cnt = min(32, end - j0);
        for (int t = 0; t < cnt; t += 4) {
            int i0 = t + sub, i1 = t + 2 + sub;
            if (i0 < cnt) {
                float e0 = s_ex2[wip][i0];
                int   s0 = s_s2 [wip][i0];
                accA = fmaf(e0, g_h2[s0 * 16 + c], accA);
            }
            if (i1 < cnt) {
                float e1 = s_ex2[wip][i1];
                int   s1 = s_s2 [wip][i1];
                accB = fmaf(e1, g_h2[s1 * 16 + c], accB);
            }
        }
        __syncwarp();
    }
    float acc = accA + accB;
    acc += __shfl_xor_sync(0xffffffffu, acc, 16);
#pragma unroll
    for (int o = 16; o >= 1; o >>= 1) den_l += __shfl_xor_sync(0xffffffffu, den_l, o);

    float v = acc / den_l + b2[c];
    float mx = v;
#pragma unroll
    for (int o = 8; o >= 1; o >>= 1) mx = fmaxf(mx, __shfl_xor_sync(0xffffffffu, mx, o, 16));
    float s = __expf(v - mx);
#pragma unroll
    for (int o = 8; o >= 1; o >>= 1) s += __shfl_xor_sync(0xffffffffu, s, o, 16);
    if (lane < 16) out[gw * 16 + c] = v - mx - logf(s);
}

// ---------------- launch ------------------------------------------------------
extern "C" void kernel_launch(void* const* d_in, const int* in_sizes, int n_in,
                              void* d_out, int out_size) {
    const float* x      = (const float*)d_in[0];
    const int*   ei     = (const int*)  d_in[1];
    const float* W1     = (const float*)d_in[2];
    const float* a_src1 = (const float*)d_in[3];
    const float* a_dst1 = (const float*)d_in[4];
    const float* b1     = (const float*)d_in[5];
    const float* W2     = (const float*)d_in[6];
    const float* a_src2 = (const float*)d_in[7];
    const float* a_dst2 = (const float*)d_in[8];
    const float* b2     = (const float*)d_in[9];
    float* out = (float*)d_out;

    const int smem1 = 2 * 128 * XSTR * sizeof(__half);   // 69632
    cudaFuncSetAttribute(k_gemm1h, cudaFuncAttributeMaxDynamicSharedMemorySize, smem1);

    k_gemm1h  <<<391, 256, smem1>>>(x, W1, a_src1, a_dst1);
    k_countmax<<<787, 256>>>(ei);
    k_scanA   <<<49, 1024>>>();
    k_scanB   <<<1, 64>>>();
    k_scanC   <<<196, 256>>>();
    k_scatter <<<782, 256>>>(ei);
    k_nodeagg1<<<6250, 256>>>(b1);
    k_gemm2   <<<3125, 256>>>(W2, a_src2, a_dst2);
    k_nodeagg2<<<6250, 256>>>(b2, out);
}